// round 1
// baseline (speedup 1.0000x reference)
#include <cuda_runtime.h>

#define RES   320
#define NB    32
#define NPIX  (RES*RES)        // 102400
#define PADN  324              // padded FFT row stride (complex elements)

// 26.2 MB scratch: gridded k-space, complex interleaved, [b][iy][ix]
__device__ float2 g_grid[NB * NPIX];

// ---------------- complex helpers ----------------
__device__ __forceinline__ float2 cadd(float2 a, float2 b){ return make_float2(a.x+b.x, a.y+b.y); }
__device__ __forceinline__ float2 csub(float2 a, float2 b){ return make_float2(a.x-b.x, a.y-b.y); }
__device__ __forceinline__ float2 cmul(float2 a, float2 b){ return make_float2(a.x*b.x - a.y*b.y, a.x*b.y + a.y*b.x); }
__device__ __forceinline__ float2 cscale(float2 a, float s){ return make_float2(a.x*s, a.y*s); }
// multiply by +i
__device__ __forceinline__ float2 cmuli(float2 a){ return make_float2(-a.y, a.x); }

// 4-point inverse DFT (exponent +i)
__device__ __forceinline__ void dft4(float2 a, float2 b, float2 c, float2 d, float2* X){
    float2 t0 = cadd(a, c), t1 = csub(a, c);
    float2 t2 = cadd(b, d), t3 = csub(b, d);
    X[0] = cadd(t0, t2);
    X[2] = csub(t0, t2);
    float2 it3 = cmuli(t3);
    X[1] = cadd(t1, it3);
    X[3] = csub(t1, it3);
}

// 8-point inverse DFT (exponent +i)
__device__ __forceinline__ void dft8(const float2* x, float2* X){
    float2 e[4], o[4];
    dft4(x[0], x[2], x[4], x[6], e);
    dft4(x[1], x[3], x[5], x[7], o);
    const float r = 0.70710678118654752f;
    float2 t0 = o[0];
    float2 t1 = make_float2(r*(o[1].x - o[1].y), r*(o[1].x + o[1].y));   // w8^1 * o1
    float2 t2 = cmuli(o[2]);                                              // w8^2 * o2
    float2 t3 = make_float2(r*(-o[3].x - o[3].y), r*(o[3].x - o[3].y));  // w8^3 * o3
    X[0] = cadd(e[0], t0); X[4] = csub(e[0], t0);
    X[1] = cadd(e[1], t1); X[5] = csub(e[1], t1);
    X[2] = cadd(e[2], t2); X[6] = csub(e[2], t2);
    X[3] = cadd(e[3], t3); X[7] = csub(e[3], t3);
}

// 5-point inverse DFT (exponent +i)
__device__ __forceinline__ void dft5(const float2* x, float2* X){
    const float c1 = 0.30901699437494742f;   // cos(72)
    const float s1 = 0.95105651629515357f;   // sin(72)
    const float c2 = -0.80901699437494745f;  // cos(144)
    const float s2 = 0.58778525229247314f;   // sin(144)
    float2 t1 = cadd(x[1], x[4]);
    float2 t2 = cadd(x[2], x[3]);
    float2 t3 = csub(x[1], x[4]);
    float2 t4 = csub(x[2], x[3]);
    X[0] = cadd(x[0], cadd(t1, t2));
    float2 a1 = cadd(x[0], cadd(cscale(t1, c1), cscale(t2, c2)));
    float2 b1 = cadd(cscale(t3, s1), cscale(t4, s2));
    float2 a2 = cadd(x[0], cadd(cscale(t1, c2), cscale(t2, c1)));
    float2 b2 = csub(cscale(t3, s2), cscale(t4, s1));
    X[1] = make_float2(a1.x - b1.y, a1.y + b1.x);   // a1 + i b1
    X[4] = make_float2(a1.x + b1.y, a1.y - b1.x);   // a1 - i b1
    X[2] = make_float2(a2.x - b2.y, a2.y + b2.x);
    X[3] = make_float2(a2.x + b2.y, a2.y - b2.x);
}

// 320-point inverse DFT (unnormalized, exponent +i), one warp per transform.
// Input natural order in A[0..319], output natural order in B[0..319].
// Decomposition: n = n1 + 64*n2 (N1=64, N2=5); X[k2 + 5*k1].
// 64-point stage: 8x8 Cooley-Tukey.
__device__ __forceinline__ void fft320(float2* A, float2* B, int lane){
    const float TWO_PI = 6.28318530717958648f;
    // ---- stage A: 64x DFT-5 (stride 64) with w320 twiddles -> B[k2*64 + n1]
    #pragma unroll
    for (int q = 0; q < 2; q++){
        int n1 = lane + 32*q;
        float2 x[5], X[5];
        #pragma unroll
        for (int j = 0; j < 5; j++) x[j] = A[n1 + 64*j];
        dft5(x, X);
        float s, c;
        __sincosf(TWO_PI * (float)n1 * (1.0f/320.0f), &s, &c);
        float2 tw = make_float2(c, s);
        float2 t  = make_float2(1.f, 0.f);
        #pragma unroll
        for (int j = 0; j < 5; j++){
            B[j*64 + n1] = cmul(X[j], t);
            t = cmul(t, tw);
        }
    }
    __syncwarp();
    // ---- stage B1: per 64-block (blk = k2_5): 8x DFT-8 over n2 (stride 8), w64 twiddle
    //      write C to A[base + j*8 + n1]
    #pragma unroll
    for (int q = 0; q < 2; q++){
        int m = lane + 32*q;
        if (m < 40){
            int blk = m >> 3, n1 = m & 7, base = blk*64;
            float2 y[8], Y[8];
            #pragma unroll
            for (int n2 = 0; n2 < 8; n2++) y[n2] = B[base + n1 + 8*n2];
            dft8(y, Y);
            float s, c;
            __sincosf(TWO_PI * (float)n1 * (1.0f/64.0f), &s, &c);
            float2 tw = make_float2(c, s);
            float2 t  = make_float2(1.f, 0.f);
            #pragma unroll
            for (int j = 0; j < 8; j++){
                A[base + j*8 + n1] = cmul(Y[j], t);
                t = cmul(t, tw);
            }
        }
    }
    __syncwarp();
    // ---- stage B2: DFT-8 over n1 (contiguous), final index blk + 5*j + 40*k1
    #pragma unroll
    for (int q = 0; q < 2; q++){
        int m = lane + 32*q;
        if (m < 40){
            int blk = m >> 3, j = m & 7, base = blk*64;
            float2 z[8], Z[8];
            #pragma unroll
            for (int n1 = 0; n1 < 8; n1++) z[n1] = A[base + j*8 + n1];
            dft8(z, Z);
            #pragma unroll
            for (int k1 = 0; k1 < 8; k1++){
                B[blk + 5*j + 40*k1] = Z[k1];
            }
        }
    }
    __syncwarp();
}

// ---------------- kernel 0: zero the grid ----------------
__global__ __launch_bounds__(256) void k_zero(){
    int i = blockIdx.x*256 + threadIdx.x;               // 1,638,400 float4s
    float4* p = reinterpret_cast<float4*>(g_grid);
    p[i] = make_float4(0.f, 0.f, 0.f, 0.f);
}

// ---------------- kernel 1: gridding (gather + weighted scatter) ----------------
// Thread order transposed (J-major, I-minor) so gathers/scatters are lane-consecutive.
// Warp-aggregated atomics neutralize the hot pixel from "skip" trajectory points.
__global__ __launch_bounds__(256) void k_gridding(const float* __restrict__ ksp,
                                                  const float* __restrict__ traj){
    int t    = blockIdx.x*256 + threadIdx.x;   // 0..102399
    int lane = threadIdx.x & 31;
    int J = t / RES;
    int I = t - J*RES;
    int p = I*RES + J;

    float tx = traj[2*p], ty = traj[2*p+1];
    float gx = tx * (2.0f/320.0f);
    float gy = ty * (2.0f/320.0f);
    float x = ((gx + 1.0f)*320.0f - 1.0f)*0.5f;
    float y = ((gy + 1.0f)*320.0f - 1.0f)*0.5f;
    float x0f = floorf(x), y0f = floorf(y);
    float fx = x - x0f, fy = y - y0f;
    int x0 = (int)x0f, y0 = (int)y0f;

    int   cx[4]  = { x0, x0+1, x0,   x0+1 };
    int   cy[4]  = { y0, y0,   y0+1, y0+1 };
    float w[4]   = { (1.f-fx)*(1.f-fy), fx*(1.f-fy), (1.f-fx)*fy, fx*fy };
    bool  val[4];
    int   idx[4];
    unsigned grp[4];
    int   cnt[4], ldr[4];

    #pragma unroll
    for (int k = 0; k < 4; k++){
        val[k] = (cx[k] >= 0) & (cx[k] < RES) & (cy[k] >= 0) & (cy[k] < RES);
        int cxc = min(RES-1, max(0, cx[k]));
        int cyc = min(RES-1, max(0, cy[k]));
        idx[k] = cyc*RES + cxc;
        int key = val[k] ? idx[k] : (-1 - lane);   // unique key for invalid lanes
        grp[k] = __match_any_sync(0xffffffffu, key);
        cnt[k] = __popc(grp[k]);
        ldr[k] = __ffs(grp[k]) - 1;
    }

    #pragma unroll
    for (int bb = 0; bb < 4; bb++){
        int b = blockIdx.y*4 + bb;
        const float* cb = ksp + (size_t)b * (RES*RES*2);
        // gather (bilinear sample)
        float sx = 0.f, sy = 0.f;
        #pragma unroll
        for (int k = 0; k < 4; k++){
            if (val[k]){
                float2 q = *reinterpret_cast<const float2*>(cb + 2*idx[k]);
                sx += q.x * w[k];
                sy += q.y * w[k];
            }
        }
        // scatter (spread back to same corners)
        float* gb = reinterpret_cast<float*>(g_grid + (size_t)b * NPIX);
        #pragma unroll
        for (int k = 0; k < 4; k++){
            if (val[k]){
                float vx = sx * w[k];
                float vy = sy * w[k];
                float* a = gb + 2*idx[k];
                if (cnt[k] == 1){
                    atomicAdd(a,   vx);
                    atomicAdd(a+1, vy);
                } else {
                    // group of lanes targeting the same pixel
                    float lx = __shfl_sync(grp[k], vx, ldr[k]);
                    float ly = __shfl_sync(grp[k], vy, ldr[k]);
                    bool same = (vx == lx) && (vy == ly);
                    if (__ballot_sync(grp[k], same) == grp[k]){
                        if (lane == ldr[k]){
                            atomicAdd(a,   vx * (float)cnt[k]);
                            atomicAdd(a+1, vy * (float)cnt[k]);
                        }
                    } else {
                        atomicAdd(a,   vx);
                        atomicAdd(a+1, vy);
                    }
                }
            }
        }
    }
}

// ---------------- kernel 2: row FFTs (last axis), in place ----------------
__global__ __launch_bounds__(256) void k_fft_rows(){
    __shared__ float2 sh[8][2][PADN];
    int warp = threadIdx.x >> 5;
    int lane = threadIdx.x & 31;
    int row  = blockIdx.x*8 + warp;       // 0 .. NB*RES-1
    float2* g = g_grid + (size_t)row * RES;
    float2* A = sh[warp][0];
    float2* B = sh[warp][1];
    #pragma unroll
    for (int i = 0; i < 10; i++) A[lane + 32*i] = g[lane + 32*i];
    __syncwarp();
    fft320(A, B, lane);
    #pragma unroll
    for (int i = 0; i < 10; i++) g[lane + 32*i] = B[lane + 32*i];
}

// ---------------- kernel 3: column FFTs + shifted/signed output store ----------------
// Each block: one batch, 8 columns. Tile-transpose through shared for coalescing.
__global__ __launch_bounds__(256) void k_fft_cols(float* __restrict__ out){
    __shared__ float2 sh[8][2][PADN];
    int warp = threadIdx.x >> 5;
    int lane = threadIdx.x & 31;
    int b  = blockIdx.x / 40;
    int v0 = (blockIdx.x % 40) * 8;

    const float2* gb = g_grid + (size_t)b * NPIX;
    // load 320x8 tile, transposed into per-warp rows
    for (int e = threadIdx.x; e < 2560; e += 256){
        int r  = e >> 3;
        int vv = e & 7;
        sh[vv][0][r] = gb[r*RES + v0 + vv];
    }
    __syncthreads();
    fft320(sh[warp][0], sh[warp][1], lane);
    __syncthreads();

    // write: out[b, comp, ni, nj] = (-1)^(u+v) * W[u, v],  ni=(u+160)%320, nj=(v+160)%320
    float* outR = out + ((size_t)b*2 + 0) * NPIX;
    float* outI = out + ((size_t)b*2 + 1) * NPIX;
    int nj0 = v0 + 160; if (nj0 >= RES) nj0 -= RES;   // 8-aligned, no wrap within block
    for (int e = threadIdx.x; e < 2560; e += 256){
        int u  = e >> 3;
        int vv = e & 7;
        float2 val = sh[vv][1][u];
        int ni = u + 160; if (ni >= RES) ni -= RES;
        float sgn = ((u + v0 + vv) & 1) ? -1.f : 1.f;
        int o = ni*RES + nj0 + vv;
        outR[o] = sgn * val.x;
        outI[o] = sgn * val.y;
    }
}

// ---------------- launch ----------------
extern "C" void kernel_launch(void* const* d_in, const int* in_sizes, int n_in,
                              void* d_out, int out_size){
    const float* ksp  = (const float*)d_in[0];   // (32,1,320,320,2) f32
    const float* traj = (const float*)d_in[1];   // (102400,2) f32
    float* out = (float*)d_out;                  // (32,1,2,320,320) f32

    k_zero<<<6400, 256>>>();
    k_gridding<<<dim3(400, 8), 256>>>(ksp, traj);
    k_fft_rows<<<NB*RES/8, 256>>>();             // 1280 blocks
    k_fft_cols<<<NB*40, 256>>>(out);             // 1280 blocks
}

// round 2
// speedup vs baseline: 1.1095x; 1.1095x over previous
#include <cuda_runtime.h>

#define RES   320
#define NB    32
#define NPIX  (RES*RES)        // 102400

// pad 1 float2 per 8 to kill shared bank conflicts in the stride-8/stride-64 FFT stages
#define PADIX(i) ((i) + ((i)>>3))
#define PADN  361              // odd => warp-to-warp stride 2*361 words*2 = 18 mod 32 (odd*2) -> transpose conflict-free

// 26.2 MB scratch: gridded k-space, complex interleaved, [b][iy][ix]
__device__ float2 g_grid[NB * NPIX];

// ---------------- complex helpers ----------------
__device__ __forceinline__ float2 cadd(float2 a, float2 b){ return make_float2(a.x+b.x, a.y+b.y); }
__device__ __forceinline__ float2 csub(float2 a, float2 b){ return make_float2(a.x-b.x, a.y-b.y); }
__device__ __forceinline__ float2 cmul(float2 a, float2 b){ return make_float2(a.x*b.x - a.y*b.y, a.x*b.y + a.y*b.x); }
__device__ __forceinline__ float2 cscale(float2 a, float s){ return make_float2(a.x*s, a.y*s); }
__device__ __forceinline__ float2 cmuli(float2 a){ return make_float2(-a.y, a.x); }

// 4-point inverse DFT (exponent +i)
__device__ __forceinline__ void dft4(float2 a, float2 b, float2 c, float2 d, float2* X){
    float2 t0 = cadd(a, c), t1 = csub(a, c);
    float2 t2 = cadd(b, d), t3 = csub(b, d);
    X[0] = cadd(t0, t2);
    X[2] = csub(t0, t2);
    float2 it3 = cmuli(t3);
    X[1] = cadd(t1, it3);
    X[3] = csub(t1, it3);
}

// 8-point inverse DFT (exponent +i)
__device__ __forceinline__ void dft8(const float2* x, float2* X){
    float2 e[4], o[4];
    dft4(x[0], x[2], x[4], x[6], e);
    dft4(x[1], x[3], x[5], x[7], o);
    const float r = 0.70710678118654752f;
    float2 t0 = o[0];
    float2 t1 = make_float2(r*(o[1].x - o[1].y), r*(o[1].x + o[1].y));   // w8^1 * o1
    float2 t2 = cmuli(o[2]);                                              // w8^2 * o2
    float2 t3 = make_float2(r*(-o[3].x - o[3].y), r*(o[3].x - o[3].y));  // w8^3 * o3
    X[0] = cadd(e[0], t0); X[4] = csub(e[0], t0);
    X[1] = cadd(e[1], t1); X[5] = csub(e[1], t1);
    X[2] = cadd(e[2], t2); X[6] = csub(e[2], t2);
    X[3] = cadd(e[3], t3); X[7] = csub(e[3], t3);
}

// 5-point inverse DFT (exponent +i)
__device__ __forceinline__ void dft5(const float2* x, float2* X){
    const float c1 = 0.30901699437494742f;
    const float s1 = 0.95105651629515357f;
    const float c2 = -0.80901699437494745f;
    const float s2 = 0.58778525229247314f;
    float2 t1 = cadd(x[1], x[4]);
    float2 t2 = cadd(x[2], x[3]);
    float2 t3 = csub(x[1], x[4]);
    float2 t4 = csub(x[2], x[3]);
    X[0] = cadd(x[0], cadd(t1, t2));
    float2 a1 = cadd(x[0], cadd(cscale(t1, c1), cscale(t2, c2)));
    float2 b1 = cadd(cscale(t3, s1), cscale(t4, s2));
    float2 a2 = cadd(x[0], cadd(cscale(t1, c2), cscale(t2, c1)));
    float2 b2 = csub(cscale(t3, s2), cscale(t4, s1));
    X[1] = make_float2(a1.x - b1.y, a1.y + b1.x);
    X[4] = make_float2(a1.x + b1.y, a1.y - b1.x);
    X[2] = make_float2(a2.x - b2.y, a2.y + b2.x);
    X[3] = make_float2(a2.x + b2.y, a2.y - b2.x);
}

// 320-point inverse DFT (unnormalized, exponent +i), one warp per transform.
// In place on padded shared buffer S (indices via PADIX). Natural order in/out.
// n = n1 + 64*n2 (N1=64, N2=5); X[k2 + 5*k1]; 64-pt stage = 8x8 Cooley-Tukey.
__device__ __forceinline__ void fft320_ip(float2* S, int lane){
    // ---- stage A: 64x DFT-5 (stride 64) with w320^{n1*j} twiddles
    float2 vA[2][5];
    #pragma unroll
    for (int q = 0; q < 2; q++){
        int n1 = lane + 32*q;
        float2 x[5], X[5];
        #pragma unroll
        for (int j = 0; j < 5; j++) x[j] = S[PADIX(n1 + 64*j)];
        dft5(x, X);
        float s, c;
        sincospif((float)n1 * (1.0f/160.0f), &s, &c);
        float2 tw = make_float2(c, s);
        float2 t  = make_float2(1.f, 0.f);
        #pragma unroll
        for (int j = 0; j < 5; j++){ vA[q][j] = cmul(X[j], t); t = cmul(t, tw); }
    }
    __syncwarp();
    #pragma unroll
    for (int q = 0; q < 2; q++){
        int n1 = lane + 32*q;
        #pragma unroll
        for (int j = 0; j < 5; j++) S[PADIX(j*64 + n1)] = vA[q][j];
    }
    __syncwarp();
    // ---- stage B1: per 64-block: 8x DFT-8 over n2 (stride 8), w64^{n1*j} twiddle
    float2 vB[2][8];
    #pragma unroll
    for (int q = 0; q < 2; q++){
        int mm = lane + 32*q;
        if (mm < 40){
            int blk = mm >> 3, n1 = mm & 7, base = blk*64;
            float2 y[8], Y[8];
            #pragma unroll
            for (int n2 = 0; n2 < 8; n2++) y[n2] = S[PADIX(base + n1 + 8*n2)];
            dft8(y, Y);
            float s, c;
            sincospif((float)n1 * (1.0f/32.0f), &s, &c);
            float2 tw = make_float2(c, s);
            float2 t  = make_float2(1.f, 0.f);
            #pragma unroll
            for (int j = 0; j < 8; j++){ vB[q][j] = cmul(Y[j], t); t = cmul(t, tw); }
        }
    }
    __syncwarp();
    #pragma unroll
    for (int q = 0; q < 2; q++){
        int mm = lane + 32*q;
        if (mm < 40){
            int blk = mm >> 3, n1 = mm & 7, base = blk*64;
            #pragma unroll
            for (int j = 0; j < 8; j++) S[PADIX(base + j*8 + n1)] = vB[q][j];
        }
    }
    __syncwarp();
    // ---- stage B2: DFT-8 over n1 (contiguous), final index blk + 5*j + 40*k1
    #pragma unroll
    for (int q = 0; q < 2; q++){
        int mm = lane + 32*q;
        if (mm < 40){
            int blk = mm >> 3, j = mm & 7, base = blk*64;
            float2 z[8], Z[8];
            #pragma unroll
            for (int n1 = 0; n1 < 8; n1++) z[n1] = S[PADIX(base + j*8 + n1)];
            dft8(z, Z);
            #pragma unroll
            for (int k1 = 0; k1 < 8; k1++) vB[q][k1] = Z[k1];
        }
    }
    __syncwarp();
    #pragma unroll
    for (int q = 0; q < 2; q++){
        int mm = lane + 32*q;
        if (mm < 40){
            int blk = mm >> 3, j = mm & 7;
            #pragma unroll
            for (int k1 = 0; k1 < 8; k1++) S[PADIX(blk + 5*j + 40*k1)] = vB[q][k1];
        }
    }
    __syncwarp();
}

// ---------------- kernel 0: zero the grid ----------------
__global__ __launch_bounds__(256) void k_zero(){
    int i = blockIdx.x*256 + threadIdx.x;               // 1,638,400 float4s
    float4* p = reinterpret_cast<float4*>(g_grid);
    p[i] = make_float4(0.f, 0.f, 0.f, 0.f);
}

// ---------------- kernel 1: gridding (gather + weighted scatter) ----------------
__device__ __forceinline__ void red_v2(float* a, float vx, float vy){
    asm volatile("red.global.add.v2.f32 [%0], {%1, %2};" :: "l"(a), "f"(vx), "f"(vy) : "memory");
}

__global__ __launch_bounds__(256) void k_gridding(const float* __restrict__ ksp,
                                                  const float* __restrict__ traj){
    int t    = blockIdx.x*256 + threadIdx.x;   // 0..102399
    int lane = threadIdx.x & 31;
    int J = t / RES;
    int I = t - J*RES;
    int p = I*RES + J;

    float tx = traj[2*p], ty = traj[2*p+1];
    float gx = tx * (2.0f/320.0f);
    float gy = ty * (2.0f/320.0f);
    float x = ((gx + 1.0f)*320.0f - 1.0f)*0.5f;
    float y = ((gy + 1.0f)*320.0f - 1.0f)*0.5f;
    float x0f = floorf(x), y0f = floorf(y);
    float fx = x - x0f, fy = y - y0f;
    int x0 = (int)x0f, y0 = (int)y0f;

    int   cx[4]  = { x0, x0+1, x0,   x0+1 };
    int   cy[4]  = { y0, y0,   y0+1, y0+1 };
    float w[4]   = { (1.f-fx)*(1.f-fy), fx*(1.f-fy), (1.f-fx)*fy, fx*fy };
    bool  val[4];
    int   idx[4];
    unsigned grp[4];
    int   cnt[4], ldr[4];

    #pragma unroll
    for (int k = 0; k < 4; k++){
        val[k] = (cx[k] >= 0) & (cx[k] < RES) & (cy[k] >= 0) & (cy[k] < RES);
        int cxc = min(RES-1, max(0, cx[k]));
        int cyc = min(RES-1, max(0, cy[k]));
        idx[k] = cyc*RES + cxc;
        int key = val[k] ? idx[k] : (-1 - lane);   // unique key for invalid lanes
        grp[k] = __match_any_sync(0xffffffffu, key);
        cnt[k] = __popc(grp[k]);
        ldr[k] = __ffs(grp[k]) - 1;
    }

    #pragma unroll
    for (int bb = 0; bb < 4; bb++){
        int b = blockIdx.y*4 + bb;
        const float* cb = ksp + (size_t)b * (RES*RES*2);
        // gather (bilinear sample)
        float sx = 0.f, sy = 0.f;
        #pragma unroll
        for (int k = 0; k < 4; k++){
            if (val[k]){
                float2 q = *reinterpret_cast<const float2*>(cb + 2*idx[k]);
                sx += q.x * w[k];
                sy += q.y * w[k];
            }
        }
        // scatter (spread back to same corners), warp-aggregated on the hot pixel
        float* gb = reinterpret_cast<float*>(g_grid + (size_t)b * NPIX);
        #pragma unroll
        for (int k = 0; k < 4; k++){
            if (val[k]){
                float vx = sx * w[k];
                float vy = sy * w[k];
                float* a = gb + 2*idx[k];
                if (cnt[k] == 1){
                    red_v2(a, vx, vy);
                } else {
                    float lx = __shfl_sync(grp[k], vx, ldr[k]);
                    float ly = __shfl_sync(grp[k], vy, ldr[k]);
                    bool same = (vx == lx) && (vy == ly);
                    if (__ballot_sync(grp[k], same) == grp[k]){
                        if (lane == ldr[k]) red_v2(a, vx * (float)cnt[k], vy * (float)cnt[k]);
                    } else {
                        red_v2(a, vx, vy);
                    }
                }
            }
        }
    }
}

// ---------------- kernel 2: row FFTs (last axis), in place ----------------
__global__ __launch_bounds__(256) void k_fft_rows(){
    __shared__ float2 sh[8][PADN];
    int warp = threadIdx.x >> 5;
    int lane = threadIdx.x & 31;
    int row  = blockIdx.x*8 + warp;       // 0 .. NB*RES-1
    float2* g = g_grid + (size_t)row * RES;
    float2* S = sh[warp];
    #pragma unroll
    for (int i = 0; i < 10; i++) S[PADIX(lane + 32*i)] = g[lane + 32*i];
    __syncwarp();
    fft320_ip(S, lane);
    #pragma unroll
    for (int i = 0; i < 10; i++) g[lane + 32*i] = S[PADIX(lane + 32*i)];
}

// ---------------- kernel 3: column FFTs + shifted/signed output store ----------------
__global__ __launch_bounds__(256) void k_fft_cols(float* __restrict__ out){
    __shared__ float2 sh[8][PADN];
    int warp = threadIdx.x >> 5;
    int lane = threadIdx.x & 31;
    int b  = blockIdx.x / 40;
    int v0 = (blockIdx.x % 40) * 8;

    const float2* gb = g_grid + (size_t)b * NPIX;
    // load 320x8 tile, transposed into per-warp rows
    for (int e = threadIdx.x; e < 2560; e += 256){
        int r  = e >> 3;
        int vv = e & 7;
        sh[vv][PADIX(r)] = gb[r*RES + v0 + vv];
    }
    __syncthreads();
    fft320_ip(sh[warp], lane);
    __syncthreads();

    // out[b, comp, ni, nj] = (-1)^(u+v) * W[u, v],  ni=(u+160)%320, nj=(v+160)%320
    float* outR = out + ((size_t)b*2 + 0) * NPIX;
    float* outI = out + ((size_t)b*2 + 1) * NPIX;
    int nj0 = v0 + 160; if (nj0 >= RES) nj0 -= RES;   // 8-aligned, no wrap within block
    for (int e = threadIdx.x; e < 2560; e += 256){
        int u  = e >> 3;
        int vv = e & 7;
        float2 val = sh[vv][PADIX(u)];
        int ni = u + 160; if (ni >= RES) ni -= RES;
        float sgn = ((u + v0 + vv) & 1) ? -1.f : 1.f;
        int o = ni*RES + nj0 + vv;
        outR[o] = sgn * val.x;
        outI[o] = sgn * val.y;
    }
}

// ---------------- launch ----------------
extern "C" void kernel_launch(void* const* d_in, const int* in_sizes, int n_in,
                              void* d_out, int out_size){
    const float* ksp  = (const float*)d_in[0];   // (32,1,320,320,2) f32
    const float* traj = (const float*)d_in[1];   // (102400,2) f32
    float* out = (float*)d_out;                  // (32,1,2,320,320) f32

    k_zero<<<6400, 256>>>();
    k_gridding<<<dim3(400, 8), 256>>>(ksp, traj);
    k_fft_rows<<<NB*RES/8, 256>>>();             // 1280 blocks
    k_fft_cols<<<NB*40, 256>>>(out);             // 1280 blocks
}

// round 4
// speedup vs baseline: 1.2200x; 1.0996x over previous
#include <cuda_runtime.h>

#define RES   320
#define NB    32
#define NPIX  (RES*RES)        // 102400

// 26.2 MB scratch: gridded k-space, complex interleaved, [b][iy][ix]
__device__ __align__(16) float2 g_grid[NB * NPIX];

// ---------------- complex helpers ----------------
__device__ __forceinline__ float2 cadd(float2 a, float2 b){ return make_float2(a.x+b.x, a.y+b.y); }
__device__ __forceinline__ float2 csub(float2 a, float2 b){ return make_float2(a.x-b.x, a.y-b.y); }
__device__ __forceinline__ float2 cmul(float2 a, float2 b){ return make_float2(a.x*b.x - a.y*b.y, a.x*b.y + a.y*b.x); }
__device__ __forceinline__ float2 cscale(float2 a, float s){ return make_float2(a.x*s, a.y*s); }

// 5-point inverse DFT (exponent +i)
__device__ __forceinline__ void dft5(const float2* x, float2* X){
    const float c1 = 0.30901699437494742f;
    const float s1 = 0.95105651629515357f;
    const float c2 = -0.80901699437494745f;
    const float s2 = 0.58778525229247314f;
    float2 t1 = cadd(x[1], x[4]);
    float2 t2 = cadd(x[2], x[3]);
    float2 t3 = csub(x[1], x[4]);
    float2 t4 = csub(x[2], x[3]);
    X[0] = cadd(x[0], cadd(t1, t2));
    float2 a1 = cadd(x[0], cadd(cscale(t1, c1), cscale(t2, c2)));
    float2 b1 = cadd(cscale(t3, s1), cscale(t4, s2));
    float2 a2 = cadd(x[0], cadd(cscale(t1, c2), cscale(t2, c1)));
    float2 b2 = csub(cscale(t3, s2), cscale(t4, s1));
    X[1] = make_float2(a1.x - b1.y, a1.y + b1.x);
    X[4] = make_float2(a1.x + b1.y, a1.y - b1.x);
    X[2] = make_float2(a2.x - b2.y, a2.y + b2.x);
    X[3] = make_float2(a2.x + b2.y, a2.y - b2.x);
}

// ---------------------------------------------------------------------------
// 320-point inverse DFT (unnormalized, exponent +i) fully in registers+shuffles.
// Decomposition: n = n1 + 10*n2 (n1 = register j 0..9, n2 = lane 0..31).
// Thread 'lane' enters holding x[10*lane + j] in v[j].
// 1) cross-lane DFT-32 over n2 (5 radix-2 DIF shuffle stages; output at lane
//    position p holds k2 = brev5(p))
// 2) per-element twiddle w320^{n1*k2}
// 3) per-lane DFT-10 over n1 (2x DFT-5 + combine)
// Thread exits holding X[32*k1 + k2] in v[k1], k2 = brev5(lane).
// ---------------------------------------------------------------------------
__device__ __forceinline__ void warp_fft320(float2* v, int lane, int k2){
    const float TWO_PI = 6.2831853071795865f;
    // stage twiddles (stages s=0..3 for m=32,16,8,4; stage 4 (m=2) has tw=1)
    float2 tws[4];
    #pragma unroll
    for (int s = 0; s < 4; s++){
        int m = 32 >> s, half = m >> 1;
        float ang = TWO_PI * (float)(lane & (half-1)) / (float)m;
        float sn, cs; __sincosf(ang, &sn, &cs);
        tws[s] = make_float2(cs, sn);
    }
    #pragma unroll
    for (int s = 0; s < 5; s++){
        int half = 16 >> s;
        bool up = (lane & half) != 0;
        #pragma unroll
        for (int j = 0; j < 10; j++){
            float ox = __shfl_xor_sync(0xffffffffu, v[j].x, half);
            float oy = __shfl_xor_sync(0xffffffffu, v[j].y, half);
            float2 r = up ? make_float2(ox - v[j].x, oy - v[j].y)
                          : make_float2(v[j].x + ox, v[j].y + oy);
            if (s < 4){
                float2 rt = cmul(r, tws[s]);
                r = up ? rt : r;
            }
            v[j] = r;
        }
    }
    // twiddle: v[j] *= w320^{j*k2}
    {
        float ang = TWO_PI * (float)k2 * (1.0f/320.0f);
        float sn, cs; __sincosf(ang, &sn, &cs);
        float2 t1 = make_float2(cs, sn);
        float2 t  = t1;
        #pragma unroll
        for (int j = 1; j < 10; j++){
            v[j] = cmul(v[j], t);
            if (j < 9) t = cmul(t, t1);
        }
    }
    // per-lane DFT-10: X[k] = E[k] + w10^k O[k]; X[k+5] = E[k] - w10^k O[k]
    {
        float2 Ein[5] = { v[0], v[2], v[4], v[6], v[8] };
        float2 Oin[5] = { v[1], v[3], v[5], v[7], v[9] };
        float2 E[5], O[5];
        dft5(Ein, E);
        dft5(Oin, O);
        const float c36 = 0.80901699437494745f, s36 = 0.58778525229247314f;
        const float c72 = 0.30901699437494742f, s72 = 0.95105651629515357f;
        const float2 w10[5] = { {1.f,0.f}, {c36,s36}, {c72,s72}, {-c72,s72}, {-c36,s36} };
        #pragma unroll
        for (int k = 0; k < 5; k++){
            float2 wo = cmul(O[k], w10[k]);
            v[k]   = cadd(E[k], wo);
            v[k+5] = csub(E[k], wo);
        }
    }
}

// ---------------- kernel 0: zero the grid ----------------
__global__ __launch_bounds__(256) void k_zero(){
    int i = blockIdx.x*256 + threadIdx.x;               // 1,638,400 float4s
    float4* p = reinterpret_cast<float4*>(g_grid);
    p[i] = make_float4(0.f, 0.f, 0.f, 0.f);
}

// ---------------- kernel 1: gridding (gather + weighted scatter) ----------------
__device__ __forceinline__ void red_v2(float* a, float vx, float vy){
    asm volatile("red.global.add.v2.f32 [%0], {%1, %2};" :: "l"(a), "f"(vx), "f"(vy) : "memory");
}

__global__ __launch_bounds__(256) void k_gridding(const float* __restrict__ ksp,
                                                  const float* __restrict__ traj){
    int t    = blockIdx.x*256 + threadIdx.x;   // 0..102399
    int lane = threadIdx.x & 31;
    int J = t / RES;
    int I = t - J*RES;
    int p = I*RES + J;

    float tx = traj[2*p], ty = traj[2*p+1];
    float gx = tx * (2.0f/320.0f);
    float gy = ty * (2.0f/320.0f);
    float x = ((gx + 1.0f)*320.0f - 1.0f)*0.5f;
    float y = ((gy + 1.0f)*320.0f - 1.0f)*0.5f;
    float x0f = floorf(x), y0f = floorf(y);
    float fx = x - x0f, fy = y - y0f;
    int x0 = (int)x0f, y0 = (int)y0f;

    int   cx[4]  = { x0, x0+1, x0,   x0+1 };
    int   cy[4]  = { y0, y0,   y0+1, y0+1 };
    float w[4]   = { (1.f-fx)*(1.f-fy), fx*(1.f-fy), (1.f-fx)*fy, fx*fy };
    bool  val[4];
    int   idx[4];
    unsigned grp[4];
    int   cnt[4], ldr[4];

    #pragma unroll
    for (int k = 0; k < 4; k++){
        val[k] = (cx[k] >= 0) & (cx[k] < RES) & (cy[k] >= 0) & (cy[k] < RES);
        int cxc = min(RES-1, max(0, cx[k]));
        int cyc = min(RES-1, max(0, cy[k]));
        idx[k] = cyc*RES + cxc;
        int key = val[k] ? idx[k] : (-1 - lane);   // unique key for invalid lanes
        grp[k] = __match_any_sync(0xffffffffu, key);
        cnt[k] = __popc(grp[k]);
        ldr[k] = __ffs(grp[k]) - 1;
    }

    #pragma unroll
    for (int bb = 0; bb < 4; bb++){
        int b = blockIdx.y*4 + bb;
        const float* cb = ksp + (size_t)b * (RES*RES*2);
        // gather (bilinear sample)
        float sx = 0.f, sy = 0.f;
        #pragma unroll
        for (int k = 0; k < 4; k++){
            if (val[k]){
                float2 q = *reinterpret_cast<const float2*>(cb + 2*idx[k]);
                sx += q.x * w[k];
                sy += q.y * w[k];
            }
        }
        // scatter (spread back to same corners), warp-aggregated on the hot pixel
        float* gb = reinterpret_cast<float*>(g_grid + (size_t)b * NPIX);
        #pragma unroll
        for (int k = 0; k < 4; k++){
            if (val[k]){
                float vx = sx * w[k];
                float vy = sy * w[k];
                float* a = gb + 2*idx[k];
                if (cnt[k] == 1){
                    red_v2(a, vx, vy);
                } else {
                    float lx = __shfl_sync(grp[k], vx, ldr[k]);
                    float ly = __shfl_sync(grp[k], vy, ldr[k]);
                    bool same = (vx == lx) && (vy == ly);
                    if (__ballot_sync(grp[k], same) == grp[k]){
                        if (lane == ldr[k]) red_v2(a, vx * (float)cnt[k], vy * (float)cnt[k]);
                    } else {
                        red_v2(a, vx, vy);
                    }
                }
            }
        }
    }
}

// ---------------- kernel 2: row FFTs (last axis), in place, no shared memory ----
__global__ __launch_bounds__(256) void k_fft_rows(){
    int warp = threadIdx.x >> 5;
    int lane = threadIdx.x & 31;
    int row  = blockIdx.x*8 + warp;       // 0 .. NB*RES-1
    float2* g = g_grid + (size_t)row * RES;

    float2 v[10];
    const float4* gv = reinterpret_cast<const float4*>(g + 10*lane);
    #pragma unroll
    for (int i = 0; i < 5; i++){
        float4 q = gv[i];
        v[2*i]   = make_float2(q.x, q.y);
        v[2*i+1] = make_float2(q.z, q.w);
    }
    int k2 = __brev((unsigned)lane) >> 27;
    warp_fft320(v, lane, k2);
    // X[32*k1 + k2]: per k1 a coalesced 256B chunk (lane-permuted)
    #pragma unroll
    for (int k1 = 0; k1 < 10; k1++) g[32*k1 + k2] = v[k1];
}

// ---------------- kernel 3: column FFTs + shifted/signed output store ----------------
// One block = one batch, 8 columns; one warp per column FFT. Shared used only
// as a transpose staging buffer ([320][9] float2 layout, ~2-way conflicts).
__global__ __launch_bounds__(256) void k_fft_cols(float* __restrict__ out){
    __shared__ float2 sh[RES][9];   // [n][col], 9 = 8 cols + 1 pad
    int warp = threadIdx.x >> 5;
    int lane = threadIdx.x & 31;
    int b  = blockIdx.x / 40;
    int v0 = (blockIdx.x % 40) * 8;

    const float2* gb = g_grid + (size_t)b * NPIX;
    // load 320x8 tile coalesced
    for (int e = threadIdx.x; e < 2560; e += 256){
        int r  = e >> 3;
        int vv = e & 7;
        sh[r][vv] = gb[r*RES + v0 + vv];
    }
    __syncthreads();

    // warp 'warp' transforms column v0+warp
    float2 v[10];
    #pragma unroll
    for (int j = 0; j < 10; j++) v[j] = sh[10*lane + j][warp];
    int k2 = __brev((unsigned)lane) >> 27;
    warp_fft320(v, lane, k2);
    __syncthreads();
    #pragma unroll
    for (int k1 = 0; k1 < 10; k1++) sh[32*k1 + k2][warp] = v[k1];
    __syncthreads();

    // out[b, comp, ni, nj] = (-1)^(u+v) * W[u, v],  ni=(u+160)%320, nj=(v+160)%320
    float* outR = out + ((size_t)b*2 + 0) * NPIX;
    float* outI = out + ((size_t)b*2 + 1) * NPIX;
    int nj0 = v0 + 160; if (nj0 >= RES) nj0 -= RES;   // 8-aligned, no wrap within block
    for (int e = threadIdx.x; e < 2560; e += 256){
        int u  = e >> 3;
        int vv = e & 7;
        float2 val = sh[u][vv];
        int ni = u + 160; if (ni >= RES) ni -= RES;
        float sgn = ((u + v0 + vv) & 1) ? -1.f : 1.f;
        int o = ni*RES + nj0 + vv;
        outR[o] = sgn * val.x;
        outI[o] = sgn * val.y;
    }
}

// ---------------- launch ----------------
extern "C" void kernel_launch(void* const* d_in, const int* in_sizes, int n_in,
                              void* d_out, int out_size){
    const float* ksp  = (const float*)d_in[0];   // (32,1,320,320,2) f32
    const float* traj = (const float*)d_in[1];   // (102400,2) f32
    float* out = (float*)d_out;                  // (32,1,2,320,320) f32

    k_zero<<<6400, 256>>>();
    k_gridding<<<dim3(400, 8), 256>>>(ksp, traj);
    k_fft_rows<<<NB*RES/8, 256>>>();             // 1280 blocks
    k_fft_cols<<<NB*40, 256>>>(out);             // 1280 blocks
}

// round 9
// speedup vs baseline: 1.7665x; 1.4480x over previous
#include <cuda_runtime.h>

#define RES   320
#define NB    32
#define NPIX  (RES*RES)        // 102400
#define NSKIP 21769.0f         // count of trajectory points zeroed by the skip mask

// 26.2 MB scratch: row-FFT output, complex interleaved, [b][iy][k-permuted]
__device__ __align__(16) float2 g_grid[NB * NPIX];

// ---------------- complex helpers ----------------
__device__ __forceinline__ float2 cadd(float2 a, float2 b){ return make_float2(a.x+b.x, a.y+b.y); }
__device__ __forceinline__ float2 csub(float2 a, float2 b){ return make_float2(a.x-b.x, a.y-b.y); }
__device__ __forceinline__ float2 cmul(float2 a, float2 b){ return make_float2(a.x*b.x - a.y*b.y, a.x*b.y + a.y*b.x); }
__device__ __forceinline__ float2 cscale(float2 a, float s){ return make_float2(a.x*s, a.y*s); }

// 5-point inverse DFT (exponent +i)
__device__ __forceinline__ void dft5(const float2* x, float2* X){
    const float c1 = 0.30901699437494742f;
    const float s1 = 0.95105651629515357f;
    const float c2 = -0.80901699437494745f;
    const float s2 = 0.58778525229247314f;
    float2 t1 = cadd(x[1], x[4]);
    float2 t2 = cadd(x[2], x[3]);
    float2 t3 = csub(x[1], x[4]);
    float2 t4 = csub(x[2], x[3]);
    X[0] = cadd(x[0], cadd(t1, t2));
    float2 a1 = cadd(x[0], cadd(cscale(t1, c1), cscale(t2, c2)));
    float2 b1 = cadd(cscale(t3, s1), cscale(t4, s2));
    float2 a2 = cadd(x[0], cadd(cscale(t1, c2), cscale(t2, c1)));
    float2 b2 = csub(cscale(t3, s2), cscale(t4, s1));
    X[1] = make_float2(a1.x - b1.y, a1.y + b1.x);
    X[4] = make_float2(a1.x + b1.y, a1.y - b1.x);
    X[2] = make_float2(a2.x - b2.y, a2.y + b2.x);
    X[3] = make_float2(a2.x + b2.y, a2.y - b2.x);
}

// ---------------------------------------------------------------------------
// 320-point inverse DFT (unnormalized, exponent +i) in registers+shuffles.
// n = n1 + 10*n2 (n1 = register j, n2 = lane). Exit: X[32*k1 + k2] in v[k1],
// k2 = brev5(lane).
// ---------------------------------------------------------------------------
__device__ __forceinline__ void warp_fft320(float2* v, int lane, int k2){
    const float TWO_PI = 6.2831853071795865f;
    float2 tws[4];
    #pragma unroll
    for (int s = 0; s < 4; s++){
        int m = 32 >> s, half = m >> 1;
        float ang = TWO_PI * (float)(lane & (half-1)) / (float)m;
        float sn, cs; __sincosf(ang, &sn, &cs);
        tws[s] = make_float2(cs, sn);
    }
    #pragma unroll
    for (int s = 0; s < 5; s++){
        int half = 16 >> s;
        bool up = (lane & half) != 0;
        #pragma unroll
        for (int j = 0; j < 10; j++){
            float ox = __shfl_xor_sync(0xffffffffu, v[j].x, half);
            float oy = __shfl_xor_sync(0xffffffffu, v[j].y, half);
            float2 r = up ? make_float2(ox - v[j].x, oy - v[j].y)
                          : make_float2(v[j].x + ox, v[j].y + oy);
            if (s < 4){
                float2 rt = cmul(r, tws[s]);
                r = up ? rt : r;
            }
            v[j] = r;
        }
    }
    {
        float ang = TWO_PI * (float)k2 * (1.0f/320.0f);
        float sn, cs; __sincosf(ang, &sn, &cs);
        float2 t1 = make_float2(cs, sn);
        float2 t  = t1;
        #pragma unroll
        for (int j = 1; j < 10; j++){
            v[j] = cmul(v[j], t);
            if (j < 9) t = cmul(t, t1);
        }
    }
    {
        float2 Ein[5] = { v[0], v[2], v[4], v[6], v[8] };
        float2 Oin[5] = { v[1], v[3], v[5], v[7], v[9] };
        float2 E[5], O[5];
        dft5(Ein, E);
        dft5(Oin, O);
        const float c36 = 0.80901699437494745f, s36 = 0.58778525229247314f;
        const float c72 = 0.30901699437494742f, s72 = 0.95105651629515357f;
        const float2 w10[5] = { {1.f,0.f}, {c36,s36}, {c72,s72}, {-c72,s72}, {-c36,s36} };
        #pragma unroll
        for (int k = 0; k < 5; k++){
            float2 wo = cmul(O[k], w10[k]);
            v[k]   = cadd(E[k], wo);
            v[k+5] = csub(E[k], wo);
        }
    }
}

// fractional coordinate, replicating the reference's fp32 op sequence exactly:
// g = t*(2/320); x = ((g+1)*320-1)*0.5; f = x - floor(x)
__device__ __forceinline__ float frac_of(int idx){
    float t = (float)(idx - 160);
    float g = t * 0.00625f;
    float x = ((g + 1.0f)*320.0f - 1.0f)*0.5f;
    return x - floorf(x);
}

// ---------------------------------------------------------------------------
// kernel 1: gridding-as-stencil + row FFTs.
// grid(qx,qy) = sum over points (I,J) in {qx,qx+1}x{qy,qy+1} of
//   m(I,J) * sx(I,qx) * sy(J,qy) * sub(I,J),
// sub(I,J) = sum of bilinear gather of c at corners {I-1,I}x{J-1,J}.
// m separable: mi(I)*mj(J). Plus hot-pixel: all skip points -> grid[0,0].
// One warp per output row qy; stencil -> registers -> warp FFT -> g_grid.
// ---------------------------------------------------------------------------
__global__ __launch_bounds__(256) void k_grid_fft_rows(const float* __restrict__ ksp){
    __shared__ float2 shc[10][322];   // rows base-1..base+8, col x at slot x+1, zero-padded
    int warp = threadIdx.x >> 5;
    int lane = threadIdx.x & 31;
    int blk  = blockIdx.x;            // 0..39
    int b    = blockIdx.y;            // batch
    int base = blk*8;
    const float2* cb = (const float2*)(ksp + (size_t)b * (2*NPIX));

    for (int idx = threadIdx.x; idx < 3200; idx += 256){
        int s = idx / 320, x = idx - s*320;
        int r = base - 1 + s;
        float2 val = (r >= 0 && r < RES) ? cb[r*RES + x] : make_float2(0.f, 0.f);
        shc[s][1 + x] = val;
    }
    if (threadIdx.x < 10){
        shc[threadIdx.x][0]   = make_float2(0.f, 0.f);
        shc[threadIdx.x][321] = make_float2(0.f, 0.f);
    }
    __syncthreads();

    int qy = base + warp;
    // y-direction gather weights for J0=qy, J1=qy+1 and scatter/mask constants
    float fy0 = frac_of(qy);
    float fy1 = frac_of(qy + 1);
    float mj0 = (!(qy >= 120 && qy <= 160)) ? 1.f : 0.f;
    float mj1 = (qy + 1 < 320 && !(qy + 1 >= 120 && qy + 1 <= 160)) ? 1.f : 0.f;
    float K0 = mj0 * fy0;            // scatter y-weight of corner qy from point J0=qy
    float K1 = mj1 * (1.0f - fy1);   // ... from point J1=qy+1
    float ay0 = 1.0f - fy0, by0 = fy0;   // gather y-weights of point J0
    float ay1 = 1.0f - fy1, by1 = fy1;   // gather y-weights of point J1

    int qx0 = 10*lane;
    float2 v[10];
    float2 TLp0, TLp1;   // previous column's left-scatter terms
    float2 cu0 = shc[warp][qx0], cv0 = shc[warp+1][qx0], cw0 = shc[warp+2][qx0];

    #pragma unroll
    for (int s = 0; s <= 10; s++){
        int I = qx0 + s;
        float2 cu1 = shc[warp  ][I+1];
        float2 cv1 = shc[warp+1][I+1];
        float2 cw1 = shc[warp+2][I+1];
        float fx = frac_of(I);
        float a = 1.0f - fx, bI = fx;
        float mi = (I < 320 && !(I >= 140 && I <= 170)) ? 1.f : 0.f;
        // x-gathered values per row (c2): a*c[r][I-1] + b*c[r][I]
        float2 cxu = make_float2(a*cu0.x + bI*cu1.x, a*cu0.y + bI*cu1.y);
        float2 cxv = make_float2(a*cv0.x + bI*cv1.x, a*cv0.y + bI*cv1.y);
        float2 cxw = make_float2(a*cw0.x + bI*cw1.x, a*cw0.y + bI*cw1.y);
        // sub(I,J0), sub(I,J1)
        float2 sub0 = make_float2(ay0*cxu.x + by0*cxv.x, ay0*cxu.y + by0*cxv.y);
        float2 sub1 = make_float2(ay1*cxv.x + by1*cxw.x, ay1*cxv.y + by1*cxw.y);
        // scatter-x weights: this column as left corner (qx=I, w=fx) / right corner (qx=I-1, w=1-fx)
        float wl = mi * bI, wr = mi * a;
        float2 TL0 = cscale(sub0, wl), TR0 = cscale(sub0, wr);
        float2 TL1 = cscale(sub1, wl), TR1 = cscale(sub1, wr);
        if (s > 0){
            float2 g;
            g.x = K0*(TLp0.x + TR0.x) + K1*(TLp1.x + TR1.x);
            g.y = K0*(TLp0.y + TR0.y) + K1*(TLp1.y + TR1.y);
            v[s-1] = g;
        }
        TLp0 = TL0; TLp1 = TL1;
        cu0 = cu1; cv0 = cv1; cw0 = cw1;
    }
    // hot pixel: 21769 skip points at (-0.5,-0.5), only valid corner (0,0), w=0.25 each way
    if (qy == 0 && lane == 0){
        float2 c00 = shc[1][1];
        v[0].x += (NSKIP * 0.0625f) * c00.x;
        v[0].y += (NSKIP * 0.0625f) * c00.y;
    }

    int k2 = __brev((unsigned)lane) >> 27;
    warp_fft320(v, lane, k2);
    float2* g = g_grid + ((size_t)b*RES + qy) * RES;
    #pragma unroll
    for (int k1 = 0; k1 < 10; k1++) g[32*k1 + k2] = v[k1];
}

// ---------------- kernel 2: column FFTs + shifted/signed output store -------
#define PADIX(i) ((i) + ((i)>>3))    // 320 -> 359 slots used
__global__ __launch_bounds__(256) void k_fft_cols(float* __restrict__ out){
    __shared__ float2 shp[8][361];   // per-column row, padded indexing
    int warp = threadIdx.x >> 5;
    int lane = threadIdx.x & 31;
    int b  = blockIdx.x / 40;
    int v0 = (blockIdx.x % 40) * 8;

    const float2* gb = g_grid + (size_t)b * NPIX;
    for (int e = threadIdx.x; e < 2560; e += 256){
        int r  = e >> 3;
        int vv = e & 7;
        shp[vv][PADIX(r)] = gb[r*RES + v0 + vv];
    }
    __syncthreads();

    // warp transforms column v0+warp (reads+writes only its own shared row)
    float2 v[10];
    #pragma unroll
    for (int j = 0; j < 10; j++) v[j] = shp[warp][PADIX(10*lane + j)];
    int k2 = __brev((unsigned)lane) >> 27;
    warp_fft320(v, lane, k2);
    #pragma unroll
    for (int k1 = 0; k1 < 10; k1++) shp[warp][PADIX(32*k1 + k2)] = v[k1];
    __syncthreads();

    // out[b, comp, ni, nj] = (-1)^(u+v) * W[u,v], ni=(u+160)%320, nj=(v+160)%320
    float* outR = out + ((size_t)b*2 + 0) * NPIX;
    float* outI = out + ((size_t)b*2 + 1) * NPIX;
    int nj0 = v0 + 160; if (nj0 >= RES) nj0 -= RES;
    for (int e = threadIdx.x; e < 2560; e += 256){
        int u  = e >> 3;
        int vv = e & 7;
        float2 val = shp[vv][PADIX(u)];
        int ni = u + 160; if (ni >= RES) ni -= RES;
        float sgn = ((u + v0 + vv) & 1) ? -1.f : 1.f;
        int o = ni*RES + nj0 + vv;
        outR[o] = sgn * val.x;
        outI[o] = sgn * val.y;
    }
}

// ---------------- launch ----------------
extern "C" void kernel_launch(void* const* d_in, const int* in_sizes, int n_in,
                              void* d_out, int out_size){
    const float* ksp = (const float*)d_in[0];   // (32,1,320,320,2) f32
    float* out = (float*)d_out;                 // (32,1,2,320,320) f32

    k_grid_fft_rows<<<dim3(40, NB), 256>>>(ksp);   // 1280 blocks
    k_fft_cols<<<NB*40, 256>>>(out);               // 1280 blocks
}

// round 13
// speedup vs baseline: 1.8594x; 1.0526x over previous
#include <cuda_runtime.h>

#define RES   320
#define NB    32
#define NPIX  (RES*RES)        // 102400
#define NSKIP 21769.0f         // count of trajectory points zeroed by the skip mask

typedef unsigned long long u64;

// 26.2 MB scratch: row-FFT output, complex packed f32x2, [b][iy][k-permuted]
__device__ __align__(16) u64 g_grid[NB * NPIX];

// ---------------- packed f32x2 helpers (sm_103a) ----------------
__device__ __forceinline__ u64 pk2(float x, float y){
    u64 r; asm("mov.b64 %0, {%1, %2};" : "=l"(r) : "r"(__float_as_uint(x)), "r"(__float_as_uint(y))); return r;
}
__device__ __forceinline__ void unpk2(u64 a, float &x, float &y){
    unsigned lo, hi;
    asm("mov.b64 {%0, %1}, %2;" : "=r"(lo), "=r"(hi) : "l"(a));
    x = __uint_as_float(lo); y = __uint_as_float(hi);
}
__device__ __forceinline__ u64 padd(u64 a, u64 b){ u64 r; asm("add.rn.f32x2 %0, %1, %2;" : "=l"(r) : "l"(a), "l"(b)); return r; }
__device__ __forceinline__ u64 pmul(u64 a, u64 b){ u64 r; asm("mul.rn.f32x2 %0, %1, %2;" : "=l"(r) : "l"(a), "l"(b)); return r; }
__device__ __forceinline__ u64 pfma(u64 a, u64 b, u64 c){ u64 r; asm("fma.rn.f32x2 %0, %1, %2, %3;" : "=l"(r) : "l"(a), "l"(b), "l"(c)); return r; }
__device__ __forceinline__ u64 bcastx(u64 a){ float x,y; unpk2(a,x,y); return pk2(x,x); }
__device__ __forceinline__ u64 bcasty(u64 a){ float x,y; unpk2(a,x,y); return pk2(y,y); }
__device__ __forceinline__ u64 rotp(u64 t){ float c,s; unpk2(t,c,s); return pk2(-s, c); }
// complex mul a * t, with t=(c,s), tr=(-s,c) packed
__device__ __forceinline__ u64 cmulp(u64 a, u64 t, u64 tr){
    return pfma(bcasty(a), tr, pmul(bcastx(a), t));
}
// a * t, rot computed inline
__device__ __forceinline__ u64 capply(u64 a, u64 t){
    return pfma(bcasty(a), rotp(t), pmul(bcastx(a), t));
}

// ---------------- packed 5-point inverse DFT (exponent +i) ----------------
__device__ __forceinline__ void dft5p(const u64* x, u64* X){
    const u64 NEG1 = pk2(-1.f, -1.f);
    const u64 C1 = pk2( 0.30901699437494742f,  0.30901699437494742f);
    const u64 C2 = pk2(-0.80901699437494745f, -0.80901699437494745f);
    const u64 S1 = pk2( 0.95105651629515357f,  0.95105651629515357f);
    const u64 S2 = pk2( 0.58778525229247314f,  0.58778525229247314f);
    const u64 NS1= pk2(-0.95105651629515357f, -0.95105651629515357f);
    u64 t1 = padd(x[1], x[4]);
    u64 t2 = padd(x[2], x[3]);
    u64 t3 = pfma(x[4], NEG1, x[1]);   // x1 - x4
    u64 t4 = pfma(x[3], NEG1, x[2]);   // x2 - x3
    X[0] = padd(x[0], padd(t1, t2));
    u64 a1 = pfma(t1, C1, pfma(t2, C2, x[0]));
    u64 b1 = pfma(t3, S1, pmul(t4, S2));
    u64 a2 = pfma(t1, C2, pfma(t2, C1, x[0]));
    u64 b2 = pfma(t4, NS1, pmul(t3, S2));
    float ax, ay, bx, by;
    unpk2(a1, ax, ay); unpk2(b1, bx, by);
    X[1] = pk2(ax - by, ay + bx);      // a1 + i b1
    X[4] = pk2(ax + by, ay - bx);      // a1 - i b1
    unpk2(a2, ax, ay); unpk2(b2, bx, by);
    X[2] = pk2(ax - by, ay + bx);
    X[3] = pk2(ax + by, ay - bx);
}

// ---------------------------------------------------------------------------
// 320-point inverse DFT (unnormalized, exponent +i), packed registers+shuffles.
// n = n1 + 10*n2 (n1 = register j, n2 = lane). Exit: X[32*k1 + k2] in v[k1],
// k2 = brev5(lane).
// ---------------------------------------------------------------------------
__device__ __forceinline__ void warp_fft320p(u64* v, int lane, int k2){
    const float TWO_PI = 6.2831853071795865f;
    const u64 NEG1  = pk2(-1.f, -1.f);
    const u64 POS1  = pk2( 1.f,  1.f);
    const u64 ONE_T = pk2( 1.f,  0.f);
    const u64 ONE_TR= pk2( 0.f,  1.f);
    // stage twiddles (stages s=0..3; stage 4 has none)
    u64 tw[4], twr[4];
    #pragma unroll
    for (int s = 0; s < 4; s++){
        int half = 16 >> s;
        float ang = TWO_PI * (float)(lane & (half-1)) / (float)(2*half);
        float sn, cs; __sincosf(ang, &sn, &cs);
        tw[s] = pk2(cs, sn); twr[s] = pk2(-sn, cs);
    }
    #pragma unroll
    for (int s = 0; s < 5; s++){
        int half = 16 >> s;
        bool up = (lane & half) != 0;
        u64 Spm = up ? NEG1 : POS1;                    // hoisted per stage
        u64 T   = (s < 4) ? (up ? tw[s]  : ONE_T ) : ONE_T;
        u64 TR  = (s < 4) ? (up ? twr[s] : ONE_TR) : ONE_TR;
        #pragma unroll
        for (int j = 0; j < 10; j++){
            float vx, vy; unpk2(v[j], vx, vy);
            float ox = __shfl_xor_sync(0xffffffffu, vx, half);
            float oy = __shfl_xor_sync(0xffffffffu, vy, half);
            u64 o = pk2(ox, oy);
            u64 r = pfma(v[j], Spm, o);                // up: o - v ; down: v + o
            if (s < 4) r = cmulp(r, T, TR);
            v[j] = r;
        }
    }
    // twiddle v[j] *= w320^{j*k2} (short-depth product tree, apply immediately)
    {
        float sn, cs;
        __sincosf(TWO_PI * (float)k2 * (1.0f/320.0f), &sn, &cs);
        u64 t1 = pk2(cs, sn), t1r = pk2(-sn, cs);
        v[1] = cmulp(v[1], t1, t1r);
        u64 t2 = cmulp(t1, t1, t1r); u64 t2r = rotp(t2);
        v[2] = cmulp(v[2], t2, t2r);
        u64 t3 = cmulp(t2, t1, t1r);
        v[3] = capply(v[3], t3);
        u64 t4 = cmulp(t2, t2, t2r); u64 t4r = rotp(t4);
        v[4] = cmulp(v[4], t4, t4r);
        u64 t5 = cmulp(t4, t1, t1r);
        v[5] = capply(v[5], t5);
        u64 t6 = cmulp(t4, t2, t2r);
        v[6] = capply(v[6], t6);
        u64 t7 = cmulp(t6, t1, t1r);
        v[7] = capply(v[7], t7);
        u64 t8 = cmulp(t4, t4, t4r);
        v[8] = capply(v[8], t8);
        u64 t9 = cmulp(t8, t1, t1r);
        v[9] = capply(v[9], t9);
    }
    // per-lane DFT-10: X[k] = E[k] + w10^k O[k]; X[k+5] = E[k] - w10^k O[k]
    {
        u64 E[5], O[5];
        { u64 ein[5] = { v[0], v[2], v[4], v[6], v[8] }; dft5p(ein, E); }
        { u64 oin[5] = { v[1], v[3], v[5], v[7], v[9] }; dft5p(oin, O); }
        const float c36 = 0.80901699437494745f, s36 = 0.58778525229247314f;
        const float c72 = 0.30901699437494742f, s72 = 0.95105651629515357f;
        v[0] = padd(E[0], O[0]);
        v[5] = pfma(O[0], NEG1, E[0]);
        {
            u64 W = pk2(c36, s36), WR = pk2(-s36, c36);
            u64 wo = cmulp(O[1], W, WR);
            v[1] = padd(E[1], wo); v[6] = pfma(wo, NEG1, E[1]);
        }
        {
            u64 W = pk2(c72, s72), WR = pk2(-s72, c72);
            u64 wo = cmulp(O[2], W, WR);
            v[2] = padd(E[2], wo); v[7] = pfma(wo, NEG1, E[2]);
        }
        {
            u64 W = pk2(-c72, s72), WR = pk2(-s72, -c72);
            u64 wo = cmulp(O[3], W, WR);
            v[3] = padd(E[3], wo); v[8] = pfma(wo, NEG1, E[3]);
        }
        {
            u64 W = pk2(-c36, s36), WR = pk2(-s36, -c36);
            u64 wo = cmulp(O[4], W, WR);
            v[4] = padd(E[4], wo); v[9] = pfma(wo, NEG1, E[4]);
        }
    }
}

// fractional coordinate, replicating the reference's fp32 op sequence exactly
__device__ __forceinline__ float frac_of(int idx){
    float t = (float)(idx - 160);
    float g = t * 0.00625f;
    float x = ((g + 1.0f)*320.0f - 1.0f)*0.5f;
    return x - floorf(x);
}

// ---------------------------------------------------------------------------
// kernel 1: gridding-as-stencil + row FFTs (packed math throughout).
// ---------------------------------------------------------------------------
__global__ __launch_bounds__(256) void k_grid_fft_rows(const float* __restrict__ ksp){
    __shared__ u64 shc[10][322];      // rows base-1..base+8, col x at slot x+1, zero-padded
    int warp = threadIdx.x >> 5;
    int lane = threadIdx.x & 31;
    int blk  = blockIdx.x;            // 0..39
    int b    = blockIdx.y;            // batch
    int base = blk*8;
    const u64* cb = (const u64*)(ksp + (size_t)b * (2*NPIX));

    for (int idx = threadIdx.x; idx < 3200; idx += 256){
        int s = idx / 320, x = idx - s*320;
        int r = base - 1 + s;
        u64 val = (r >= 0 && r < RES) ? cb[r*RES + x] : 0ull;
        shc[s][1 + x] = val;
    }
    if (threadIdx.x < 10){
        shc[threadIdx.x][0]   = 0ull;
        shc[threadIdx.x][321] = 0ull;
    }
    __syncthreads();

    int qy = base + warp;
    float fy0 = frac_of(qy);
    float fy1 = frac_of(qy + 1);
    float mj0 = (!(qy >= 120 && qy <= 160)) ? 1.f : 0.f;
    float mj1 = (qy + 1 < 320 && !(qy + 1 >= 120 && qy + 1 <= 160)) ? 1.f : 0.f;
    u64 K0p  = pk2(mj0 * fy0,          mj0 * fy0);          // scatter-y: corner qy from J0=qy
    u64 K1p  = pk2(mj1 * (1.0f - fy1), mj1 * (1.0f - fy1)); //            from J1=qy+1
    u64 AY0  = pk2(1.0f - fy0, 1.0f - fy0);
    u64 BY0  = pk2(fy0, fy0);
    u64 AY1  = pk2(1.0f - fy1, 1.0f - fy1);
    u64 BY1  = pk2(fy1, fy1);

    int qx0 = 10*lane;
    u64 v[10];
    u64 TLp0 = 0ull, TLp1 = 0ull;
    u64 cu0 = shc[warp][qx0], cv0 = shc[warp+1][qx0], cw0 = shc[warp+2][qx0];

    #pragma unroll
    for (int s = 0; s <= 10; s++){
        int I = qx0 + s;
        u64 cu1 = shc[warp  ][I+1];
        u64 cv1 = shc[warp+1][I+1];
        u64 cw1 = shc[warp+2][I+1];
        float fx = frac_of(I);
        float a = 1.0f - fx;
        float mi = (I < 320 && !(I >= 140 && I <= 170)) ? 1.f : 0.f;
        u64 Ap = pk2(a, a), Bp = pk2(fx, fx);
        // x-gathered values per row: a*c[r][I-1] + fx*c[r][I]
        u64 cxu = pfma(cu1, Bp, pmul(cu0, Ap));
        u64 cxv = pfma(cv1, Bp, pmul(cv0, Ap));
        u64 cxw = pfma(cw1, Bp, pmul(cw0, Ap));
        // sub(I,J0), sub(I,J1)
        u64 sub0 = pfma(cxv, BY0, pmul(cxu, AY0));
        u64 sub1 = pfma(cxw, BY1, pmul(cxv, AY1));
        // scatter-x weights: left corner (qx=I, w=fx) / right corner (qx=I-1, w=1-fx)
        u64 WL = pk2(mi*fx, mi*fx), WR = pk2(mi*a, mi*a);
        u64 TL0 = pmul(sub0, WL), TR0 = pmul(sub0, WR);
        u64 TL1 = pmul(sub1, WL), TR1 = pmul(sub1, WR);
        if (s > 0){
            v[s-1] = pfma(padd(TLp1, TR1), K1p, pmul(padd(TLp0, TR0), K0p));
        }
        TLp0 = TL0; TLp1 = TL1;
        cu0 = cu1; cv0 = cv1; cw0 = cw1;
    }
    // hot pixel: 21769 skip points at (-0.5,-0.5), only valid corner (0,0)
    if (qy == 0 && lane == 0){
        u64 c00 = shc[1][1];
        v[0] = pfma(c00, pk2(NSKIP*0.0625f, NSKIP*0.0625f), v[0]);
    }

    int k2 = __brev((unsigned)lane) >> 27;
    warp_fft320p(v, lane, k2);
    u64* g = g_grid + ((size_t)b*RES + qy) * RES;
    #pragma unroll
    for (int k1 = 0; k1 < 10; k1++) g[32*k1 + k2] = v[k1];
}

// ---------------- kernel 2: column FFTs + shifted/signed output store -------
#define PADIX(i) ((i) + ((i)>>3))    // 320 -> 359 slots used
__global__ __launch_bounds__(256) void k_fft_cols(float* __restrict__ out){
    __shared__ u64 shp[8][361];      // per-column row, padded indexing
    int warp = threadIdx.x >> 5;
    int lane = threadIdx.x & 31;
    int b  = blockIdx.x / 40;
    int v0 = (blockIdx.x % 40) * 8;

    const u64* gb = g_grid + (size_t)b * NPIX;
    for (int e = threadIdx.x; e < 2560; e += 256){
        int r  = e >> 3;
        int vv = e & 7;
        shp[vv][PADIX(r)] = gb[r*RES + v0 + vv];
    }
    __syncthreads();

    // warp transforms column v0+warp (reads+writes only its own shared row)
    u64 v[10];
    #pragma unroll
    for (int j = 0; j < 10; j++) v[j] = shp[warp][PADIX(10*lane + j)];
    int k2 = __brev((unsigned)lane) >> 27;
    warp_fft320p(v, lane, k2);
    #pragma unroll
    for (int k1 = 0; k1 < 10; k1++) shp[warp][PADIX(32*k1 + k2)] = v[k1];
    __syncthreads();

    // out[b, comp, ni, nj] = (-1)^(u+v) * W[u,v], ni=(u+160)%320, nj=(v+160)%320
    float* outR = out + ((size_t)b*2 + 0) * NPIX;
    float* outI = out + ((size_t)b*2 + 1) * NPIX;
    int nj0 = v0 + 160; if (nj0 >= RES) nj0 -= RES;
    for (int e = threadIdx.x; e < 2560; e += 256){
        int u  = e >> 3;
        int vv = e & 7;
        float sx, sy; unpk2(shp[vv][PADIX(u)], sx, sy);
        int ni = u + 160; if (ni >= RES) ni -= RES;
        float sgn = ((u + v0 + vv) & 1) ? -1.f : 1.f;
        int o = ni*RES + nj0 + vv;
        outR[o] = sgn * sx;
        outI[o] = sgn * sy;
    }
}

// ---------------- launch ----------------
extern "C" void kernel_launch(void* const* d_in, const int* in_sizes, int n_in,
                              void* d_out, int out_size){
    const float* ksp = (const float*)d_in[0];   // (32,1,320,320,2) f32
    float* out = (float*)d_out;                 // (32,1,2,320,320) f32

    k_grid_fft_rows<<<dim3(40, NB), 256>>>(ksp);   // 1280 blocks
    k_fft_cols<<<NB*40, 256>>>(out);               // 1280 blocks
}

// round 15
// speedup vs baseline: 1.9579x; 1.0530x over previous
#include <cuda_runtime.h>

#define RES   320
#define NB    32
#define NPIX  (RES*RES)        // 102400
#define NSKIP 21769.0f         // count of trajectory points zeroed by the skip mask

typedef unsigned long long u64;

// 26.2 MB scratch: row-FFT output, complex packed (re,im) u64, [b][iy][k-permuted]
__device__ __align__(16) u64 g_grid[NB * NPIX];

// ---------------- packed f32x2 helpers (sm_103a) ----------------
__device__ __forceinline__ u64 pk2(float x, float y){
    u64 r; asm("mov.b64 %0, {%1, %2};" : "=l"(r) : "r"(__float_as_uint(x)), "r"(__float_as_uint(y))); return r;
}
__device__ __forceinline__ void unpk2(u64 a, float &x, float &y){
    unsigned lo, hi;
    asm("mov.b64 {%0, %1}, %2;" : "=r"(lo), "=r"(hi) : "l"(a));
    x = __uint_as_float(lo); y = __uint_as_float(hi);
}
__device__ __forceinline__ u64 padd(u64 a, u64 b){ u64 r; asm("add.rn.f32x2 %0, %1, %2;" : "=l"(r) : "l"(a), "l"(b)); return r; }
__device__ __forceinline__ u64 pmul(u64 a, u64 b){ u64 r; asm("mul.rn.f32x2 %0, %1, %2;" : "=l"(r) : "l"(a), "l"(b)); return r; }
__device__ __forceinline__ u64 pfma(u64 a, u64 b, u64 c){ u64 r; asm("fma.rn.f32x2 %0, %1, %2, %3;" : "=l"(r) : "l"(a), "l"(b), "l"(c)); return r; }

// ---------------- SoA packed 5-point inverse DFT (exponent +i) --------------
// xr/xi hold re/im of TWO transforms in the two f32x2 halves.
__device__ __forceinline__ void dft5_soa(const u64* xr, const u64* xi, u64* Xr, u64* Xi){
    const u64 NEG1 = pk2(-1.f, -1.f);
    const u64 C1 = pk2( 0.30901699437494742f,  0.30901699437494742f);
    const u64 C2 = pk2(-0.80901699437494745f, -0.80901699437494745f);
    const u64 S1 = pk2( 0.95105651629515357f,  0.95105651629515357f);
    const u64 S2 = pk2( 0.58778525229247314f,  0.58778525229247314f);
    const u64 NS1= pk2(-0.95105651629515357f, -0.95105651629515357f);
    u64 t1r = padd(xr[1], xr[4]), t1i = padd(xi[1], xi[4]);
    u64 t2r = padd(xr[2], xr[3]), t2i = padd(xi[2], xi[3]);
    u64 t3r = pfma(xr[4], NEG1, xr[1]), t3i = pfma(xi[4], NEG1, xi[1]);
    u64 t4r = pfma(xr[3], NEG1, xr[2]), t4i = pfma(xi[3], NEG1, xi[2]);
    Xr[0] = padd(xr[0], padd(t1r, t2r));
    Xi[0] = padd(xi[0], padd(t1i, t2i));
    u64 a1r = pfma(t1r, C1, pfma(t2r, C2, xr[0])), a1i = pfma(t1i, C1, pfma(t2i, C2, xi[0]));
    u64 b1r = pfma(t4r, S2, pmul(t3r, S1)),        b1i = pfma(t4i, S2, pmul(t3i, S1));
    u64 a2r = pfma(t1r, C2, pfma(t2r, C1, xr[0])), a2i = pfma(t1i, C2, pfma(t2i, C1, xi[0]));
    u64 b2r = pfma(t4r, NS1, pmul(t3r, S2)),       b2i = pfma(t4i, NS1, pmul(t3i, S2));
    // X1 = a1 + i b1 ; X4 = a1 - i b1 ; X2 = a2 + i b2 ; X3 = a2 - i b2
    Xr[1] = pfma(b1i, NEG1, a1r);  Xi[1] = padd(a1i, b1r);
    Xr[4] = padd(a1r, b1i);        Xi[4] = pfma(b1r, NEG1, a1i);
    Xr[2] = pfma(b2i, NEG1, a2r);  Xi[2] = padd(a2i, b2r);
    Xr[3] = padd(a2r, b2i);        Xi[3] = pfma(b2r, NEG1, a2i);
}

// ---------------------------------------------------------------------------
// Dual 320-point inverse DFT (unnormalized, exponent +i), SoA across the two
// f32x2 halves. re[j]/im[j] hold element n = j + 10*lane of transforms A (.x)
// and B (.y). Exit: element X[32*k1 + k2] in re[k1]/im[k1], k2 = brev5(lane).
// ---------------------------------------------------------------------------
__device__ __forceinline__ void warp_fft320_soa(u64* re, u64* im, int lane, int k2){
    const float TWO_PI = 6.2831853071795865f;
    const u64 POS1 = pk2(1.f, 1.f);
    const u64 NEG1 = pk2(-1.f, -1.f);
    float twc[4], twn[4];
    #pragma unroll
    for (int s = 0; s < 4; s++){
        int half = 16 >> s;
        float ang = TWO_PI * (float)(lane & (half-1)) / (float)(2*half);
        __sincosf(ang, &twn[s], &twc[s]);
    }
    #pragma unroll
    for (int s = 0; s < 5; s++){
        int half = 16 >> s;
        bool up = (lane & half) != 0;
        u64 Spm = up ? NEG1 : POS1;
        u64 C = POS1, S = 0ull, NS = 0ull;
        if (s < 4 && up){ C = pk2(twc[s], twc[s]); S = pk2(twn[s], twn[s]); NS = pk2(-twn[s], -twn[s]); }
        #pragma unroll
        for (int j = 0; j < 10; j++){
            float ax, ay;
            unpk2(re[j], ax, ay);
            float bx = __shfl_xor_sync(0xffffffffu, ax, half);
            float by = __shfl_xor_sync(0xffffffffu, ay, half);
            u64 rr = pfma(re[j], Spm, pk2(bx, by));     // up: o - v ; down: v + o
            unpk2(im[j], ax, ay);
            bx = __shfl_xor_sync(0xffffffffu, ax, half);
            by = __shfl_xor_sync(0xffffffffu, ay, half);
            u64 ri = pfma(im[j], Spm, pk2(bx, by));
            if (s < 4){
                re[j] = pfma(ri, NS, pmul(rr, C));      // rr*c - ri*s
                im[j] = pfma(ri, C,  pmul(rr, S));      // rr*s + ri*c
            } else { re[j] = rr; im[j] = ri; }
        }
    }
    // twiddle v[j] *= w320^{j*k2}, scalar angle tree, packed apply
    {
        float s1, c1;
        __sincosf(TWO_PI * (float)k2 * (1.0f/320.0f), &s1, &c1);
        float cj = c1, sj = s1;
        #pragma unroll
        for (int j = 1; j < 10; j++){
            u64 C = pk2(cj, cj), S = pk2(sj, sj), NS = pk2(-sj, -sj);
            u64 t   = pmul(re[j], C);
            u64 nim = pfma(im[j], C, pmul(re[j], S));
            re[j] = pfma(im[j], NS, t);
            im[j] = nim;
            if (j < 9){
                float cn = cj*c1 - sj*s1;
                float sn = cj*s1 + sj*c1;
                cj = cn; sj = sn;
            }
        }
    }
    // per-lane DFT-10
    {
        u64 Er[5], Ei[5], Or[5], Oi[5];
        {
            u64 xr[5] = { re[0], re[2], re[4], re[6], re[8] };
            u64 xi[5] = { im[0], im[2], im[4], im[6], im[8] };
            dft5_soa(xr, xi, Er, Ei);
        }
        {
            u64 xr[5] = { re[1], re[3], re[5], re[7], re[9] };
            u64 xi[5] = { im[1], im[3], im[5], im[7], im[9] };
            dft5_soa(xr, xi, Or, Oi);
        }
        const float wc[5] = {1.f, 0.80901699437494745f, 0.30901699437494742f, -0.30901699437494742f, -0.80901699437494745f};
        const float ws[5] = {0.f, 0.58778525229247314f, 0.95105651629515357f,  0.95105651629515357f,  0.58778525229247314f};
        #pragma unroll
        for (int k = 0; k < 5; k++){
            u64 wor, woi;
            if (k == 0){ wor = Or[0]; woi = Oi[0]; }
            else {
                u64 C = pk2(wc[k], wc[k]), S = pk2(ws[k], ws[k]), NS = pk2(-ws[k], -ws[k]);
                wor = pfma(Oi[k], NS, pmul(Or[k], C));
                woi = pfma(Oi[k], C,  pmul(Or[k], S));
            }
            re[k]   = padd(Er[k], wor);
            im[k]   = padd(Ei[k], woi);
            re[k+5] = pfma(wor, NEG1, Er[k]);
            im[k+5] = pfma(woi, NEG1, Ei[k]);
        }
    }
}

// fractional coordinate, replicating the reference's fp32 op sequence exactly
__device__ __forceinline__ float frac_of(int idx){
    float t = (float)(idx - 160);
    float g = t * 0.00625f;
    float x = ((g + 1.0f)*320.0f - 1.0f)*0.5f;
    return x - floorf(x);
}

// ---------------------------------------------------------------------------
// gridding stencil for one output row qy. rowU/rowV/rowW are shc row pointers
// (col x at slot x+1). Produces v[10] = (re,im)-packed grid row elements at
// columns 10*lane .. 10*lane+9.
// ---------------------------------------------------------------------------
__device__ __forceinline__ void stencil_row(const u64* rowU, const u64* rowV, const u64* rowW,
                                            int qy, int lane, u64* v){
    float fy0 = frac_of(qy);
    float fy1 = frac_of(qy + 1);
    float mj0 = (!(qy >= 120 && qy <= 160)) ? 1.f : 0.f;
    float mj1 = (qy + 1 < 320 && !(qy + 1 >= 120 && qy + 1 <= 160)) ? 1.f : 0.f;
    u64 K0p = pk2(mj0 * fy0,          mj0 * fy0);
    u64 K1p = pk2(mj1 * (1.0f - fy1), mj1 * (1.0f - fy1));
    u64 AY0 = pk2(1.0f - fy0, 1.0f - fy0);
    u64 BY0 = pk2(fy0, fy0);
    u64 AY1 = pk2(1.0f - fy1, 1.0f - fy1);
    u64 BY1 = pk2(fy1, fy1);

    int qx0 = 10*lane;
    u64 TLp0 = 0ull, TLp1 = 0ull;
    u64 cu0 = rowU[qx0], cv0 = rowV[qx0], cw0 = rowW[qx0];

    #pragma unroll
    for (int s = 0; s <= 10; s++){
        int I = qx0 + s;
        u64 cu1 = rowU[I+1];
        u64 cv1 = rowV[I+1];
        u64 cw1 = rowW[I+1];
        float fx = frac_of(I);
        float a = 1.0f - fx;
        float mi = (I < 320 && !(I >= 140 && I <= 170)) ? 1.f : 0.f;
        u64 Ap = pk2(a, a), Bp = pk2(fx, fx);
        u64 cxu = pfma(cu1, Bp, pmul(cu0, Ap));
        u64 cxv = pfma(cv1, Bp, pmul(cv0, Ap));
        u64 cxw = pfma(cw1, Bp, pmul(cw0, Ap));
        u64 sub0 = pfma(cxv, BY0, pmul(cxu, AY0));
        u64 sub1 = pfma(cxw, BY1, pmul(cxv, AY1));
        u64 WL = pk2(mi*fx, mi*fx), WR = pk2(mi*a, mi*a);
        u64 TL0 = pmul(sub0, WL), TR0 = pmul(sub0, WR);
        u64 TL1 = pmul(sub1, WL), TR1 = pmul(sub1, WR);
        if (s > 0){
            v[s-1] = pfma(padd(TLp1, TR1), K1p, pmul(padd(TLp0, TR0), K0p));
        }
        TLp0 = TL0; TLp1 = TL1;
        cu0 = cu1; cv0 = cv1; cw0 = cw1;
    }
}

// ---------------------------------------------------------------------------
// kernel 1: gridding-as-stencil + dual row FFTs. Block = 8 warps x 2 rows.
// ---------------------------------------------------------------------------
__global__ __launch_bounds__(256) void k_grid_fft_rows(const float* __restrict__ ksp){
    __shared__ u64 shc[18][322];      // rows base-1..base+16, col x at slot x+1
    int warp = threadIdx.x >> 5;
    int lane = threadIdx.x & 31;
    int base = blockIdx.x * 16;       // 0..304
    int b    = blockIdx.y;
    const u64* cb = (const u64*)(ksp + (size_t)b * (2*NPIX));

    for (int idx = threadIdx.x; idx < 18*320; idx += 256){
        int s = idx / 320, x = idx - 320*s;
        int r = base - 1 + s;
        shc[s][1 + x] = (r >= 0 && r < RES) ? cb[r*RES + x] : 0ull;
    }
    if (threadIdx.x < 36){
        int s = threadIdx.x >> 1;
        shc[s][(threadIdx.x & 1) ? 321 : 0] = 0ull;
    }
    __syncthreads();

    int qyA = base + 2*warp;
    u64 vA[10], vB[10];
    stencil_row(shc[2*warp],   shc[2*warp+1], shc[2*warp+2], qyA,     lane, vA);
    stencil_row(shc[2*warp+1], shc[2*warp+2], shc[2*warp+3], qyA + 1, lane, vB);
    // hot pixel: 21769 skip points at (-0.5,-0.5), only valid corner (0,0)
    if (qyA == 0 && lane == 0){
        vA[0] = pfma(shc[1][1], pk2(NSKIP*0.0625f, NSKIP*0.0625f), vA[0]);
    }

    // repack to SoA: re = (reA, reB), im = (imA, imB)
    u64 re[10], im[10];
    #pragma unroll
    for (int j = 0; j < 10; j++){
        float ax, ay, bx, by;
        unpk2(vA[j], ax, ay);
        unpk2(vB[j], bx, by);
        re[j] = pk2(ax, bx);
        im[j] = pk2(ay, by);
    }
    int k2 = __brev((unsigned)lane) >> 27;
    warp_fft320_soa(re, im, lane, k2);

    u64* gA = g_grid + ((size_t)b*RES + qyA) * RES;
    u64* gB = gA + RES;
    #pragma unroll
    for (int k1 = 0; k1 < 10; k1++){
        float rA, rB, iA, iB;
        unpk2(re[k1], rA, rB);
        unpk2(im[k1], iA, iB);
        gA[32*k1 + k2] = pk2(rA, iA);
        gB[32*k1 + k2] = pk2(rB, iB);
    }
}

// ---------------- kernel 2: dual column FFTs + shifted/signed output --------
#define PADIX(i) ((i) + ((i)>>3))
__global__ __launch_bounds__(256) void k_fft_cols(float* __restrict__ out){
    __shared__ u64 shre[8][361], shim[8][361];   // SoA: column pair per warp
    int warp = threadIdx.x >> 5;
    int lane = threadIdx.x & 31;
    int b  = blockIdx.x / 20;
    int v0 = (blockIdx.x % 20) * 16;

    const u64* gb = g_grid + (size_t)b * NPIX;
    for (int e = threadIdx.x; e < 2560; e += 256){
        int r = e >> 3, pp = e & 7;
        float4 q = *(const float4*)(gb + r*RES + v0 + 2*pp);   // cols v0+2pp, v0+2pp+1
        shre[pp][PADIX(r)] = pk2(q.x, q.z);
        shim[pp][PADIX(r)] = pk2(q.y, q.w);
    }
    __syncthreads();

    u64 re[10], im[10];
    #pragma unroll
    for (int j = 0; j < 10; j++){
        re[j] = shre[warp][PADIX(10*lane + j)];
        im[j] = shim[warp][PADIX(10*lane + j)];
    }
    int k2 = __brev((unsigned)lane) >> 27;
    warp_fft320_soa(re, im, lane, k2);
    #pragma unroll
    for (int k1 = 0; k1 < 10; k1++){
        shre[warp][PADIX(32*k1 + k2)] = re[k1];
        shim[warp][PADIX(32*k1 + k2)] = im[k1];
    }
    __syncthreads();

    // out[b, comp, ni, nj] = (-1)^(u+v) * W[u,v], ni=(u+160)%320, nj=(v+160)%320
    float* outR = out + ((size_t)b*2 + 0) * NPIX;
    float* outI = out + ((size_t)b*2 + 1) * NPIX;
    int nj0 = v0 + 160; if (nj0 >= RES) nj0 -= RES;
    for (int e = threadIdx.x; e < 2560; e += 256){
        int u = e >> 3, pp = e & 7;
        float rA, rB, iA, iB;
        unpk2(shre[pp][PADIX(u)], rA, rB);
        unpk2(shim[pp][PADIX(u)], iA, iB);
        int ni = u + 160; if (ni >= RES) ni -= RES;
        int colA = v0 + 2*pp;
        float sgnA = ((u + colA) & 1) ? -1.f : 1.f;
        float sgnB = -sgnA;
        int o = ni*RES + nj0 + 2*pp;
        *(float2*)(outR + o) = make_float2(sgnA*rA, sgnB*rB);
        *(float2*)(outI + o) = make_float2(sgnA*iA, sgnB*iB);
    }
}

// ---------------- launch ----------------
extern "C" void kernel_launch(void* const* d_in, const int* in_sizes, int n_in,
                              void* d_out, int out_size){
    const float* ksp = (const float*)d_in[0];   // (32,1,320,320,2) f32
    float* out = (float*)d_out;                 // (32,1,2,320,320) f32

    k_grid_fft_rows<<<dim3(20, NB), 256>>>(ksp);   // 640 blocks, 2 rows/warp
    k_fft_cols<<<NB*20, 256>>>(out);               // 640 blocks, 2 cols/warp
}